// round 1
// baseline (speedup 1.0000x reference)
#include <cuda_runtime.h>
#include <cstdint>

typedef unsigned long long u64;

// ---- packed f32x2 helpers (sm_103a) ----
__device__ __forceinline__ u64 pack2(float lo, float hi) {
    u64 r; asm("mov.b64 %0, {%1, %2};" : "=l"(r) : "f"(lo), "f"(hi)); return r;
}
__device__ __forceinline__ void unpack2(u64 v, float& lo, float& hi) {
    asm("mov.b64 {%0, %1}, %2;" : "=f"(lo), "=f"(hi) : "l"(v));
}
__device__ __forceinline__ u64 fma2(u64 a, u64 b, u64 c) {
    u64 d; asm("fma.rn.f32x2 %0, %1, %2, %3;" : "=l"(d) : "l"(a), "l"(b), "l"(c));
    return d;
}

#define TPB 256
#define MAX_PAL 1024         // palette capacity in shared (actual M = 128)
#define MAX_BLOCKS 2048

__device__ float g_partials[MAX_BLOCKS];

// Per palette entry j we precompute splatted pairs:
//   s_a[j] = { pack2(px,px), pack2(py,py) }
//   s_b[j] = { pack2(pz,pz), pack2(c,c) }   with c = 0.5*(px^2+py^2+pz^2)
// Inner loop per 2 points: score2 = fma2(nx2, pxx, fma2(ny2, pyy, fma2(nz2, pzz, cc)))
// where nx2 = pack2(-x0, -x1) etc.  min over j of score gives
//   d = sqrt(max(|x|^2 + 2*min_score, 0)).

__global__ void __launch_bounds__(TPB)
ncd_main(const float* __restrict__ pts, const float* __restrict__ pal,
         int N, int M)
{
    __shared__ ulonglong2 s_a[MAX_PAL];
    __shared__ ulonglong2 s_b[MAX_PAL];

    const int tid = threadIdx.x;

    // Build splatted palette in shared (uniform-address broadcast reads later).
    for (int j = tid; j < M; j += TPB) {
        float px = pal[3 * j + 0];
        float py = pal[3 * j + 1];
        float pz = pal[3 * j + 2];
        float c  = 0.5f * (px * px + py * py + pz * pz);
        s_a[j] = make_ulonglong2(pack2(px, px), pack2(py, py));
        s_b[j] = make_ulonglong2(pack2(pz, pz), pack2(c, c));
    }
    __syncthreads();

    float tsum = 0.0f;
    const long long stride = (long long)gridDim.x * TPB * 2;

    for (long long i0 = ((long long)blockIdx.x * TPB + tid) * 2; i0 < N; i0 += stride) {
        const long long i1 = i0 + 1;
        const bool v1 = (i1 < (long long)N);

        float x0 = pts[i0 * 3 + 0];
        float y0 = pts[i0 * 3 + 1];
        float z0 = pts[i0 * 3 + 2];
        float x1 = x0, y1 = y0, z1 = z0;
        if (v1) {
            x1 = pts[i0 * 3 + 3];
            y1 = pts[i0 * 3 + 4];
            z1 = pts[i0 * 3 + 5];
        }

        const u64 nx2 = pack2(-x0, -x1);
        const u64 ny2 = pack2(-y0, -y1);
        const u64 nz2 = pack2(-z0, -z1);
        const float n0 = __fmaf_rn(x0, x0, __fmaf_rn(y0, y0, z0 * z0));
        const float n1 = __fmaf_rn(x1, x1, __fmaf_rn(y1, y1, z1 * z1));

        // Two independent min-accumulator sets to break the FMNMX dep chain.
        float mA_lo = 1e30f, mA_hi = 1e30f;
        float mB_lo = 1e30f, mB_hi = 1e30f;

        int j = 0;
        #pragma unroll 4
        for (; j + 2 <= M; j += 2) {
            const ulonglong2 a0 = s_a[j];
            const ulonglong2 b0 = s_b[j];
            const ulonglong2 a1 = s_a[j + 1];
            const ulonglong2 b1 = s_b[j + 1];
            const u64 sc0 = fma2(nx2, a0.x, fma2(ny2, a0.y, fma2(nz2, b0.x, b0.y)));
            const u64 sc1 = fma2(nx2, a1.x, fma2(ny2, a1.y, fma2(nz2, b1.x, b1.y)));
            float lo, hi;
            unpack2(sc0, lo, hi);
            mA_lo = fminf(mA_lo, lo);
            mA_hi = fminf(mA_hi, hi);
            unpack2(sc1, lo, hi);
            mB_lo = fminf(mB_lo, lo);
            mB_hi = fminf(mB_hi, hi);
        }
        for (; j < M; j++) {  // tail (not taken for M=128)
            const ulonglong2 a0 = s_a[j];
            const ulonglong2 b0 = s_b[j];
            const u64 sc0 = fma2(nx2, a0.x, fma2(ny2, a0.y, fma2(nz2, b0.x, b0.y)));
            float lo, hi;
            unpack2(sc0, lo, hi);
            mA_lo = fminf(mA_lo, lo);
            mA_hi = fminf(mA_hi, hi);
        }

        const float m0 = fminf(mA_lo, mB_lo);
        const float m1 = fminf(mA_hi, mB_hi);
        const float d0 = sqrtf(fmaxf(__fmaf_rn(2.0f, m0, n0), 0.0f));
        const float d1 = sqrtf(fmaxf(__fmaf_rn(2.0f, m1, n1), 0.0f));
        tsum += d0;
        if (v1) tsum += d1;
    }

    // ---- block reduction (deterministic) ----
    #pragma unroll
    for (int o = 16; o; o >>= 1) tsum += __shfl_down_sync(0xFFFFFFFFu, tsum, o);

    __shared__ float s_warp[TPB / 32];
    if ((tid & 31) == 0) s_warp[tid >> 5] = tsum;
    __syncthreads();
    if (tid < 32) {
        float v = (tid < TPB / 32) ? s_warp[tid] : 0.0f;
        #pragma unroll
        for (int o = 16; o; o >>= 1) v += __shfl_down_sync(0xFFFFFFFFu, v, o);
        if (tid == 0) g_partials[blockIdx.x] = v;
    }
}

__global__ void __launch_bounds__(256)
ncd_reduce(float* __restrict__ out, int nb, float invN)
{
    const int tid = threadIdx.x;
    float sum = 0.0f;
    for (int i = tid; i < nb; i += 256) sum += g_partials[i];

    #pragma unroll
    for (int o = 16; o; o >>= 1) sum += __shfl_down_sync(0xFFFFFFFFu, sum, o);

    __shared__ float s_warp[8];
    if ((tid & 31) == 0) s_warp[tid >> 5] = sum;
    __syncthreads();
    if (tid < 32) {
        float v = (tid < 8) ? s_warp[tid] : 0.0f;
        #pragma unroll
        for (int o = 16; o; o >>= 1) v += __shfl_down_sync(0xFFFFFFFFu, v, o);
        if (tid == 0) out[0] = v * invN;
    }
}

extern "C" void kernel_launch(void* const* d_in, const int* in_sizes, int n_in,
                              void* d_out, int out_size)
{
    const float* pts = (const float*)d_in[0];   // output_colors (N,3)
    const float* pal = (const float*)d_in[1];   // target_palette (M,3)
    float* out = (float*)d_out;

    const int N = in_sizes[0] / 3;
    int M = in_sizes[1] / 3;
    if (M > MAX_PAL) M = MAX_PAL;  // dataset has M=128

    int blocks = (int)(((long long)N + (long long)TPB * 2 - 1) / ((long long)TPB * 2));
    if (blocks > MAX_BLOCKS) blocks = MAX_BLOCKS;
    if (blocks < 1) blocks = 1;

    ncd_main<<<blocks, TPB>>>(pts, pal, N, M);
    ncd_reduce<<<1, 256>>>(out, blocks, 1.0f / (float)N);
}